// round 1
// baseline (speedup 1.0000x reference)
#include <cuda_runtime.h>
#include <cstdint>

// lct_fk: f-k migration pipeline.
//   data = sqrt(relu(f * (t/127)^2)), zero-pad 128^3 -> 256^3
//   F = fftn(data); fre = fftshift(F)
//   samp = trilinear(fre at Stolt coords) * zmask * |gz|/(gznew+1e-8)
//   out = real(ifftn(fftshift(samp)))[:128,:128,:128]
// Both fftshifts are folded into index arithmetic. x/y interp is an exact
// half-sample shift -> fixed 0.25-weight 2x2 stencil; only z interpolates.

#define LL 256
#define VOLS 2

__device__ float2 g_A[(size_t)VOLS * LL * LL * LL]; // 268 MB
__device__ float2 g_B[(size_t)VOLS * LL * LL * LL]; // 268 MB

__device__ __forceinline__ int brev8(int i) { return (int)(__brev((unsigned)i) >> 24); }

// ---------------- 256-pt radix-2 DIT FFT helpers (shared memory) -------------
// dir = +1 : forward (exp(-i...)), dir = -1 : inverse (exp(+i...), unnormalized)

__device__ __forceinline__ void fft256_single(float2* sh, int tid /*0..127*/, float dir) {
#pragma unroll
    for (int s = 1; s <= 8; ++s) {
        int m = 1 << s, half = m >> 1;
        __syncthreads();
        int j = tid;
        int k = j & (half - 1);
        int i0 = ((j >> (s - 1)) << s) + k;
        int i1 = i0 + half;
        float ang = dir * (-6.283185307179586f) * (float)k / (float)m;
        float sn, cs;
        __sincosf(ang, &sn, &cs);
        float2 a = sh[i0];
        float2 b = sh[i1];
        float tx = b.x * cs - b.y * sn;
        float ty = b.x * sn + b.y * cs;
        sh[i0] = make_float2(a.x + tx, a.y + ty);
        sh[i1] = make_float2(a.x - tx, a.y - ty);
    }
    __syncthreads();
}

// 16 lines per block, padded to 257 to avoid cross-line bank conflicts.
__device__ __forceinline__ void fft256_multi16(float2 (*sh)[257], int tid /*0..255*/, float dir) {
#pragma unroll
    for (int s = 1; s <= 8; ++s) {
        int m = 1 << s, half = m >> 1;
        __syncthreads();
#pragma unroll
        for (int it = 0; it < 8; ++it) {
            int w = tid + it * 256;         // 16 lines * 128 butterflies = 2048
            int line = w >> 7;
            int j = w & 127;
            int k = j & (half - 1);
            int i0 = ((j >> (s - 1)) << s) + k;
            int i1 = i0 + half;
            float ang = dir * (-6.283185307179586f) * (float)k / (float)m;
            float sn, cs;
            __sincosf(ang, &sn, &cs);
            float2 a = sh[line][i0];
            float2 b = sh[line][i1];
            float tx = b.x * cs - b.y * sn;
            float ty = b.x * sn + b.y * cs;
            sh[line][i0] = make_float2(a.x + tx, a.y + ty);
            sh[line][i1] = make_float2(a.x - tx, a.y - ty);
        }
    }
    __syncthreads();
}

// ---------------- Pass 1: preprocess + forward FFT along x ------------------
// Only t<128, h<128 lines are nonzero; write full 256 x outputs to A.
__global__ void k_fwd_x(const float* __restrict__ in) {
    __shared__ float2 sh[256];
    int h = blockIdx.x, t = blockIdx.y, v = blockIdx.z;
    int tid = threadIdx.x; // 128
    float g = (float)t * (1.0f / 127.0f);
    float f = in[(((size_t)v * 128 + t) * 128 + h) * 128 + tid];
    float x = f * g * g;
    float val = (x > 0.0f) ? sqrtf(x) : 0.0f;
    sh[brev8(tid)] = make_float2(val, 0.0f);
    sh[brev8(tid + 128)] = make_float2(0.0f, 0.0f);
    fft256_single(sh, tid, 1.0f);
    size_t base = (((size_t)v * LL + t) * LL + h) * LL;
    g_A[base + tid] = sh[tid];
    g_A[base + tid + 128] = sh[tid + 128];
}

// ---------------- Pass 2: forward FFT along h (t<128 only) -----------------
__global__ void k_fwd_h() {
    __shared__ float2 sh[16][257];
    int xt = blockIdx.x, t = blockIdx.y, v = blockIdx.z;
    int tid = threadIdx.x;          // 256
    int tx = tid & 15, q = tid >> 4;
    int x0 = xt * 16;
    size_t base = ((size_t)v * LL + t) * LL * LL + (x0 + tx);
    for (int h = q; h < 256; h += 16) {
        float2 vv = (h < 128) ? g_A[base + (size_t)h * LL] : make_float2(0.f, 0.f);
        sh[tx][brev8(h)] = vv;
    }
    fft256_multi16(sh, tid, 1.0f);
    for (int h = q; h < 256; h += 16)
        g_A[base + (size_t)h * LL] = sh[tx][h];
}

// ---------------- Pass 3: forward FFT along t (all h, x) -------------------
__global__ void k_fwd_t() {
    __shared__ float2 sh[16][257];
    int xt = blockIdx.x, h = blockIdx.y, v = blockIdx.z;
    int tid = threadIdx.x;
    int tx = tid & 15, q = tid >> 4;
    int x0 = xt * 16;
    size_t base = (size_t)v * LL * LL * LL + (size_t)h * LL + (x0 + tx);
    for (int t = q; t < 256; t += 16) {
        float2 vv = (t < 128) ? g_A[base + (size_t)t * LL * LL] : make_float2(0.f, 0.f);
        sh[tx][brev8(t)] = vv;
    }
    fft256_multi16(sh, tid, 1.0f);
    for (int t = q; t < 256; t += 16)
        g_A[base + (size_t)t * LL * LL] = sh[tx][t];
}

// ---------------- Pass 4: Stolt resampling -> B (unshifted) ----------------
// G[uz,uy,ux] nonzero only for uz in [1,127]. iz = uz+128 (>=129 satisfies
// zmask automatically). fre(z,y,x) = F[(z+128)&255][(y+128)&255][(x+128)&255].
__global__ void k_sample() {
    int ux = threadIdx.x;        // 0..255
    int uy = blockIdx.x;         // 0..255
    int uz = blockIdx.y + 1;     // 1..127
    int v  = blockIdx.z;

    int iy = (uy + 128) & 255;
    int ix = (ux + 128) & 255;
    float gz = (float)uz * (1.0f / 128.0f);
    float gx = (float)(ix - 128) * (1.0f / 128.0f);
    float gy = (float)(iy - 128) * (1.0f / 128.0f);
    const float fk = 0.1024f; // (N*trange/(M*width*4))^2
    float gznew = sqrtf(fk * (gx * gx + gy * gy) + gz * gz);
    float pz = ((gznew + 1.0f) * 256.0f - 1.0f) * 0.5f;
    float z0f = floorf(pz);
    float dz = pz - z0f;
    int z0 = (int)z0f;
    float scale = 0.25f * gz / (gznew + 1e-8f);

    const float2* __restrict__ F = g_A + (size_t)v * LL * LL * LL;
    float accx = 0.0f, accy = 0.0f;
#pragma unroll
    for (int zz = 0; zz < 2; ++zz) {
        int zc = z0 + zz;
        if (zc < 0 || zc >= 256) continue;
        float wz = zz ? dz : (1.0f - dz);
        size_t zb = (size_t)((zc + 128) & 255) * LL * LL;
#pragma unroll
        for (int a = 0; a < 2; ++a) {
            int ys = iy - 1 + a;
            if (ys < 0 || ys >= 256) continue;
            size_t yb = zb + (size_t)((ys + 128) & 255) * LL;
#pragma unroll
            for (int bb = 0; bb < 2; ++bb) {
                int xs = ix - 1 + bb;
                if (xs < 0 || xs >= 256) continue;
                float2 fv = F[yb + ((xs + 128) & 255)];
                accx += wz * fv.x;
                accy += wz * fv.y;
            }
        }
    }
    size_t o = (((size_t)v * LL + uz) * LL + uy) * LL + ux;
    g_B[o] = make_float2(accx * scale, accy * scale);
}

// ---------------- Pass 5: inverse FFT along t (in: B z 1..127, out: A t<128)
__global__ void k_inv_t() {
    __shared__ float2 sh[16][257];
    int xt = blockIdx.x, uy = blockIdx.y, v = blockIdx.z;
    int tid = threadIdx.x;
    int tx = tid & 15, q = tid >> 4;
    int x0 = xt * 16;
    size_t baseB = (size_t)v * LL * LL * LL + (size_t)uy * LL + (x0 + tx);
    for (int t = q; t < 256; t += 16) {
        float2 vv = (t >= 1 && t < 128) ? g_B[baseB + (size_t)t * LL * LL]
                                        : make_float2(0.f, 0.f);
        sh[tx][brev8(t)] = vv;
    }
    fft256_multi16(sh, tid, -1.0f);
    size_t baseA = baseB; // same geometry, different buffer
    for (int t = q; t < 128; t += 16)
        g_A[baseA + (size_t)t * LL * LL] = sh[tx][t];
}

// ---------------- Pass 6: inverse FFT along h (t<128; out h<128, in place) -
__global__ void k_inv_h() {
    __shared__ float2 sh[16][257];
    int xt = blockIdx.x, t = blockIdx.y, v = blockIdx.z; // t in 0..127
    int tid = threadIdx.x;
    int tx = tid & 15, q = tid >> 4;
    int x0 = xt * 16;
    size_t base = ((size_t)v * LL + t) * LL * LL + (x0 + tx);
    for (int h = q; h < 256; h += 16)
        sh[tx][brev8(h)] = g_A[base + (size_t)h * LL];
    fft256_multi16(sh, tid, -1.0f);
    for (int h = q; h < 128; h += 16)
        g_A[base + (size_t)h * LL] = sh[tx][h];
}

// ---------------- Pass 7: inverse FFT along x + real crop + normalize ------
__global__ void k_inv_x(float* __restrict__ out) {
    __shared__ float2 sh[256];
    int h = blockIdx.x, t = blockIdx.y, v = blockIdx.z; // h,t in 0..127
    int tid = threadIdx.x; // 128
    size_t base = (((size_t)v * LL + t) * LL + h) * LL;
    sh[brev8(tid)] = g_A[base + tid];
    sh[brev8(tid + 128)] = g_A[base + tid + 128];
    fft256_single(sh, tid, -1.0f);
    out[(((size_t)v * 128 + t) * 128 + h) * 128 + tid] =
        sh[tid].x * (1.0f / 16777216.0f); // 1/256^3 ifft normalization
}

extern "C" void kernel_launch(void* const* d_in, const int* in_sizes, int n_in,
                              void* d_out, int out_size) {
    (void)in_sizes; (void)n_in; (void)out_size;
    const float* in = (const float*)d_in[0];
    float* out = (float*)d_out;

    k_fwd_x<<<dim3(128, 128, VOLS), 128>>>(in);
    k_fwd_h<<<dim3(16, 128, VOLS), 256>>>();
    k_fwd_t<<<dim3(16, 256, VOLS), 256>>>();
    k_sample<<<dim3(256, 127, VOLS), 256>>>();
    k_inv_t<<<dim3(16, 256, VOLS), 256>>>();
    k_inv_h<<<dim3(16, 128, VOLS), 256>>>();
    k_inv_x<<<dim3(128, 128, VOLS), 128>>>(out);
}

// round 2
// speedup vs baseline: 1.0416x; 1.0416x over previous
#include <cuda_runtime.h>
#include <cstdint>

// lct_fk: f-k migration pipeline, round 2.
// Key facts exploited:
//  - pz = 128*gznew + 127.5, gznew >= 1/128  =>  z0 >= 128 always, so the
//    sampler reads only unshifted F t-planes [0,127]. fwd_t writes half.
//  - Stolt sampling fused into the inverse-t FFT (buffer B for samples gone;
//    g_B reused as the inverse-pipeline buffer).
//  - x/y interp is an exact half-sample shift -> fixed 0.25-weight 2x2 stencil.

#define LL 256
#define VOLS 2

__device__ float2 g_A[(size_t)VOLS * LL * LL * LL]; // forward spectrum
__device__ float2 g_B[(size_t)VOLS * LL * LL * LL]; // inverse pipeline

__device__ __forceinline__ int brev8(int i) { return (int)(__brev((unsigned)i) >> 24); }

// ---------------- 256-pt radix-2 DIT FFT helpers (shared memory) -------------
__device__ __forceinline__ void fft256_single(float2* sh, int tid /*0..127*/, float dir) {
#pragma unroll
    for (int s = 1; s <= 8; ++s) {
        int m = 1 << s, half = m >> 1;
        __syncthreads();
        int j = tid;
        int k = j & (half - 1);
        int i0 = ((j >> (s - 1)) << s) + k;
        int i1 = i0 + half;
        float ang = dir * (-6.283185307179586f) * (float)k / (float)m;
        float sn, cs;
        __sincosf(ang, &sn, &cs);
        float2 a = sh[i0];
        float2 b = sh[i1];
        float tx = b.x * cs - b.y * sn;
        float ty = b.x * sn + b.y * cs;
        sh[i0] = make_float2(a.x + tx, a.y + ty);
        sh[i1] = make_float2(a.x - tx, a.y - ty);
    }
    __syncthreads();
}

// 16 lines per block, padded to 257 to avoid cross-line bank conflicts.
__device__ __forceinline__ void fft256_multi16(float2 (*sh)[257], int tid /*0..255*/, float dir) {
#pragma unroll
    for (int s = 1; s <= 8; ++s) {
        int m = 1 << s, half = m >> 1;
        __syncthreads();
#pragma unroll
        for (int it = 0; it < 8; ++it) {
            int w = tid + it * 256;
            int line = w >> 7;
            int j = w & 127;
            int k = j & (half - 1);
            int i0 = ((j >> (s - 1)) << s) + k;
            int i1 = i0 + half;
            float ang = dir * (-6.283185307179586f) * (float)k / (float)m;
            float sn, cs;
            __sincosf(ang, &sn, &cs);
            float2 a = sh[line][i0];
            float2 b = sh[line][i1];
            float tx = b.x * cs - b.y * sn;
            float ty = b.x * sn + b.y * cs;
            sh[line][i0] = make_float2(a.x + tx, a.y + ty);
            sh[line][i1] = make_float2(a.x - tx, a.y - ty);
        }
    }
    __syncthreads();
}

// ---------------- Pass 1: preprocess + forward FFT along x ------------------
__global__ void k_fwd_x(const float* __restrict__ in) {
    __shared__ float2 sh[256];
    int h = blockIdx.x, t = blockIdx.y, v = blockIdx.z;
    int tid = threadIdx.x; // 128
    float g = (float)t * (1.0f / 127.0f);
    float f = in[(((size_t)v * 128 + t) * 128 + h) * 128 + tid];
    float x = f * g * g;
    float val = (x > 0.0f) ? sqrtf(x) : 0.0f;
    sh[brev8(tid)] = make_float2(val, 0.0f);
    sh[brev8(tid + 128)] = make_float2(0.0f, 0.0f);
    fft256_single(sh, tid, 1.0f);
    size_t base = (((size_t)v * LL + t) * LL + h) * LL;
    g_A[base + tid] = sh[tid];
    g_A[base + tid + 128] = sh[tid + 128];
}

// ---------------- Pass 2: forward FFT along h (t<128 only, in place) --------
__global__ void k_fwd_h() {
    __shared__ float2 sh[16][257];
    int xt = blockIdx.x, t = blockIdx.y, v = blockIdx.z;
    int tid = threadIdx.x; // 256
    int tx = tid & 15, q = tid >> 4;
    int x0 = xt * 16;
    size_t base = ((size_t)v * LL + t) * LL * LL + (x0 + tx);
    for (int h = q; h < 256; h += 16) {
        float2 vv = (h < 128) ? g_A[base + (size_t)h * LL] : make_float2(0.f, 0.f);
        sh[tx][brev8(h)] = vv;
    }
    fft256_multi16(sh, tid, 1.0f);
    for (int h = q; h < 256; h += 16)
        g_A[base + (size_t)h * LL] = sh[tx][h];
}

// ---------------- Pass 3: forward FFT along t; only t<128 outputs needed ----
__global__ void k_fwd_t() {
    __shared__ float2 sh[16][257];
    int xt = blockIdx.x, h = blockIdx.y, v = blockIdx.z;
    int tid = threadIdx.x;
    int tx = tid & 15, q = tid >> 4;
    int x0 = xt * 16;
    size_t base = (size_t)v * LL * LL * LL + (size_t)h * LL + (x0 + tx);
    for (int t = q; t < 256; t += 16) {
        float2 vv = (t < 128) ? g_A[base + (size_t)t * LL * LL] : make_float2(0.f, 0.f);
        sh[tx][brev8(t)] = vv;
    }
    fft256_multi16(sh, tid, 1.0f);
    for (int t = q; t < 128; t += 16)          // sampler never reads t>=128
        g_A[base + (size_t)t * LL * LL] = sh[tx][t];
}

// ---- Pass 4 (fused): Stolt sampling -> inverse FFT along t -> g_B (t<128) --
// Each thread handles 8 consecutive uz so the z0-plane sums S(z) are reused
// (z0 advances by 0 or 1 per uz step since dpz/duz = gz/gznew <= 1).
__global__ void k_samp_inv_t() {
    __shared__ float2 sh[16][257];
    int xt = blockIdx.x, uy = blockIdx.y, v = blockIdx.z;
    int tid = threadIdx.x;  // 256
    int tx = tid & 15, q = tid >> 4;
    int ux = xt * 16 + tx;

    // zero the whole line buffer
    for (int t = q; t < 256; t += 16) sh[tx][t] = make_float2(0.f, 0.f);
    __syncthreads();

    int iy = (uy + 128) & 255;
    int ixs = (ux + 128) & 255;
    float gx = (float)(ixs - 128) * (1.0f / 128.0f);
    float gy = (float)(iy - 128) * (1.0f / 128.0f);
    const float fk = 0.1024f;
    float rxy = fk * (gx * gx + gy * gy);

    // the 2x2 xy stencil is z-independent: precompute valid plane offsets
    unsigned offs[4];
    int nofs = 0;
#pragma unroll
    for (int a = 0; a < 2; ++a) {
        int ys = iy - 1 + a;
        if (ys < 0 || ys >= 256) continue;
        unsigned yo = (unsigned)((ys + 128) & 255) * LL;
#pragma unroll
        for (int bb = 0; bb < 2; ++bb) {
            int xs = ixs - 1 + bb;
            if (xs < 0 || xs >= 256) continue;
            offs[nofs++] = yo + (unsigned)((xs + 128) & 255);
        }
    }

    const float2* __restrict__ F = g_A + (size_t)v * LL * LL * LL;

    auto planeSum = [&](int zc, float& sx, float& sy) {
        sx = 0.f; sy = 0.f;
        if (zc > 255) return;                 // zc >= 128 guaranteed
        size_t zb = (size_t)(zc - 128) * LL * LL;   // unshifted plane in [0,127]
        for (int i = 0; i < nofs; ++i) {
            float2 fv = F[zb + offs[i]];
            sx += fv.x; sy += fv.y;
        }
    };

    int czA = -5, czB = -5;
    float SAx = 0.f, SAy = 0.f, SBx = 0.f, SBy = 0.f;
    int t0 = (q == 0) ? 1 : q * 8;
    int t1 = q * 8 + 8;
    for (int t = t0; t < t1; ++t) {
        float gz = (float)t * (1.0f / 128.0f);
        float gznew = sqrtf(rxy + gz * gz);
        float pz = 128.0f * gznew + 127.5f;   // >= 128.5
        int z0 = (int)pz;
        float dz = pz - (float)z0;
        float S0x, S0y, S1x, S1y;
        if (z0 == czA) {                      // both planes cached
            S0x = SAx; S0y = SAy; S1x = SBx; S1y = SBy;
        } else if (z0 == czB) {               // shifted by one: reuse upper
            S0x = SBx; S0y = SBy;
            planeSum(z0 + 1, S1x, S1y);
        } else {
            planeSum(z0, S0x, S0y);
            planeSum(z0 + 1, S1x, S1y);
        }
        czA = z0; SAx = S0x; SAy = S0y;
        czB = z0 + 1; SBx = S1x; SBy = S1y;
        float scale = 0.25f * gz / (gznew + 1e-8f);
        sh[tx][brev8(t)] = make_float2((S0x * (1.f - dz) + S1x * dz) * scale,
                                       (S0y * (1.f - dz) + S1y * dz) * scale);
    }

    fft256_multi16(sh, tid, -1.0f);           // stage-1 sync orders the scatter

    size_t baseB = (size_t)v * LL * LL * LL + (size_t)uy * LL + ux;
    for (int t = q; t < 128; t += 16)
        g_B[baseB + (size_t)t * LL * LL] = sh[tx][t];
}

// ---------------- Pass 5: inverse FFT along h (t<128; out h<128, in place) --
__global__ void k_inv_h() {
    __shared__ float2 sh[16][257];
    int xt = blockIdx.x, t = blockIdx.y, v = blockIdx.z; // t in 0..127
    int tid = threadIdx.x;
    int tx = tid & 15, q = tid >> 4;
    int x0 = xt * 16;
    size_t base = ((size_t)v * LL + t) * LL * LL + (x0 + tx);
    for (int h = q; h < 256; h += 16)
        sh[tx][brev8(h)] = g_B[base + (size_t)h * LL];
    fft256_multi16(sh, tid, -1.0f);
    for (int h = q; h < 128; h += 16)
        g_B[base + (size_t)h * LL] = sh[tx][h];
}

// ---------------- Pass 6: inverse FFT along x + real crop + normalize -------
__global__ void k_inv_x(float* __restrict__ out) {
    __shared__ float2 sh[256];
    int h = blockIdx.x, t = blockIdx.y, v = blockIdx.z; // h,t in 0..127
    int tid = threadIdx.x; // 128
    size_t base = (((size_t)v * LL + t) * LL + h) * LL;
    sh[brev8(tid)] = g_B[base + tid];
    sh[brev8(tid + 128)] = g_B[base + tid + 128];
    fft256_single(sh, tid, -1.0f);
    out[(((size_t)v * 128 + t) * 128 + h) * 128 + tid] =
        sh[tid].x * (1.0f / 16777216.0f); // 1/256^3 ifft normalization
}

extern "C" void kernel_launch(void* const* d_in, const int* in_sizes, int n_in,
                              void* d_out, int out_size) {
    (void)in_sizes; (void)n_in; (void)out_size;
    const float* in = (const float*)d_in[0];
    float* out = (float*)d_out;

    k_fwd_x<<<dim3(128, 128, VOLS), 128>>>(in);
    k_fwd_h<<<dim3(16, 128, VOLS), 256>>>();
    k_fwd_t<<<dim3(16, 256, VOLS), 256>>>();
    k_samp_inv_t<<<dim3(16, 256, VOLS), 256>>>();
    k_inv_h<<<dim3(16, 128, VOLS), 256>>>();
    k_inv_x<<<dim3(128, 128, VOLS), 128>>>(out);
}

// round 4
// speedup vs baseline: 3.3271x; 3.1941x over previous
#include <cuda_runtime.h>
#include <cstdint>

// lct_fk round 4: radix-16^2 register FFTs (2 smem round trips instead of 8),
// x/y half-sample stencil folded into forward FFT passes as an exact circular
// pair-filter G[k]=0.5(X[k]+X[k-1]) (exception: G[128]=0.5*X[128]).
// FIX vs r3: sampler reads filtered spectrum at UNSHIFTED (uy,ux), not (iy,ix).

#define LL 256
#define VOLS 2

__device__ float2 g_A[(size_t)VOLS * LL * LL * LL]; // forward (filtered) spectrum
__device__ float2 g_B[(size_t)VOLS * LL * LL * LL]; // inverse pipeline

// 4-bit bit reversal
__device__ const int BR4[16] = {0,8,4,12,2,10,6,14,1,9,5,13,3,11,7,15};

// ---------------- 16-pt in-register DIT FFT (input bit-reversed) ------------
__device__ __forceinline__ void fft16(float2 r[16], float dir) {
    const float CT[8] = {1.f, 0.92387953f, 0.70710678f, 0.38268343f,
                         0.f, -0.38268343f, -0.70710678f, -0.92387953f};
    const float ST[8] = {0.f, -0.38268343f, -0.70710678f, -0.92387953f,
                         -1.f, -0.92387953f, -0.70710678f, -0.38268343f};
#pragma unroll
    for (int s = 1; s <= 4; ++s) {
        int half = 1 << (s - 1);
#pragma unroll
        for (int j = 0; j < 8; ++j) {
            int k = j & (half - 1);
            int i0 = ((j >> (s - 1)) << s) + k;
            int i1 = i0 + half;
            float cs = CT[k << (4 - s)];
            float sn = dir * ST[k << (4 - s)];
            float2 b = r[i1];
            float tx = b.x * cs - b.y * sn;
            float ty = b.x * sn + b.y * cs;
            float2 a = r[i0];
            r[i1] = make_float2(a.x - tx, a.y - ty);
            r[i0] = make_float2(a.x + tx, a.y + ty);
        }
    }
}

// inter-pass twiddle: r[k1] *= exp(dir * -2*pi*i * j*k1 / 256)
__device__ __forceinline__ void twiddle16(float2 r[16], int j, float dir) {
#pragma unroll
    for (int k1 = 1; k1 < 16; ++k1) {
        float sn, cs;
        __sincosf(dir * -0.024543692606f * (float)(j * k1), &sn, &cs);
        float2 a = r[k1];
        r[k1] = make_float2(a.x * cs - a.y * sn, a.x * sn + a.y * cs);
    }
}

// Full 256-pt FFT for one line handled by 16 threads (role j).
// r on entry: r[BR4[n1]] = x[16*n1 + j]. On exit: r[k2] = X[j + 16*k2].
__device__ __forceinline__ void fft256_pass(float2 r[16], float2* Tline,
                                            int j, float dir) {
    fft16(r, dir);
    twiddle16(r, j, dir);
    __syncthreads();
#pragma unroll
    for (int k1 = 0; k1 < 16; ++k1) Tline[k1 * 17 + j] = r[k1];
    __syncthreads();
    float2 rr[16];
#pragma unroll
    for (int n2 = 0; n2 < 16; ++n2) rr[BR4[n2]] = Tline[j * 17 + n2];
    fft16(rr, dir);
#pragma unroll
    for (int k = 0; k < 16; ++k) r[k] = rr[k];
}

// ---------------- Pass 1: preprocess + x-FFT + x-filter ---------------------
__global__ void k_fwd_x(const float* __restrict__ in) {
    __shared__ float2 T[16][273];
    int tid = threadIdx.x;
    int j = tid & 15, ln = tid >> 4;
    int h = blockIdx.x * 16 + ln, t = blockIdx.y, v = blockIdx.z;
    float g = (float)t * (1.0f / 127.0f);
    const float* src = in + (((size_t)v * 128 + t) * 128 + h) * 128;
    float2 r[16];
#pragma unroll
    for (int n1 = 0; n1 < 16; ++n1) {
        float val = 0.0f;
        if (n1 < 8) {
            float f = src[16 * n1 + j];
            float xx = f * g * g;
            val = (xx > 0.0f) ? sqrtf(xx) : 0.0f;
        }
        r[BR4[n1]] = make_float2(val, 0.0f);
    }
    fft256_pass(r, T[ln], j, 1.0f);
    __syncthreads();
#pragma unroll
    for (int k2 = 0; k2 < 16; ++k2) T[ln][j + 17 * k2] = r[k2]; // pidx(k)=k+(k>>4)
    __syncthreads();
    float2* dst = g_A + (((size_t)v * LL + t) * LL + h) * LL;
#pragma unroll
    for (int k2 = 0; k2 < 16; ++k2) {
        int k = j + 16 * k2;
        float2 a = T[ln][k + (k >> 4)];
        float2 b = make_float2(0.f, 0.f);
        if (k != 128) { int km = (k - 1) & 255; b = T[ln][km + (km >> 4)]; }
        dst[k] = make_float2(0.5f * (a.x + b.x), 0.5f * (a.y + b.y));
    }
}

// ---------------- Pass 2: h-FFT (reads h<128) + y-filter, writes all h ------
__global__ void k_fwd_h() {
    __shared__ float2 T[16][273];
    int tid = threadIdx.x;
    int tx = tid & 15, j = tid >> 4;
    int x = blockIdx.x * 16 + tx, t = blockIdx.y, v = blockIdx.z;
    size_t base = ((size_t)v * LL + t) * LL * LL + x;
    float2 r[16];
#pragma unroll
    for (int n1 = 0; n1 < 16; ++n1) {
        int hh = 16 * n1 + j;
        r[BR4[n1]] = (n1 < 8) ? g_A[base + (size_t)hh * LL] : make_float2(0.f, 0.f);
    }
    fft256_pass(r, T[tx], j, 1.0f);
    __syncthreads();
#pragma unroll
    for (int k2 = 0; k2 < 16; ++k2) T[tx][j + 17 * k2] = r[k2];
    __syncthreads();
#pragma unroll
    for (int k2 = 0; k2 < 16; ++k2) {
        int k = j + 16 * k2;
        float2 a = T[tx][k + (k >> 4)];
        float2 b = make_float2(0.f, 0.f);
        if (k != 128) { int km = (k - 1) & 255; b = T[tx][km + (km >> 4)]; }
        g_A[base + (size_t)k * LL] =
            make_float2(0.5f * (a.x + b.x), 0.5f * (a.y + b.y));
    }
}

// ---------------- Pass 3: t-FFT (reads t<128, writes t<128) -----------------
__global__ void k_fwd_t() {
    __shared__ float2 T[16][273];
    int tid = threadIdx.x;
    int tx = tid & 15, j = tid >> 4;
    int x = blockIdx.x * 16 + tx, h = blockIdx.y, v = blockIdx.z;
    size_t base = (size_t)v * LL * LL * LL + (size_t)h * LL + x;
    float2 r[16];
#pragma unroll
    for (int n1 = 0; n1 < 16; ++n1) {
        int tt = 16 * n1 + j;
        r[BR4[n1]] = (n1 < 8) ? g_A[base + (size_t)tt * LL * LL] : make_float2(0.f, 0.f);
    }
    fft256_pass(r, T[tx], j, 1.0f);
#pragma unroll
    for (int k2 = 0; k2 < 8; ++k2)   // j + 16*k2 < 128
        g_A[base + (size_t)(j + 16 * k2) * LL * LL] = r[k2];
}

// ---- Pass 4 (fused): Stolt sample (single-point, filtered) + inverse t-FFT -
__global__ void k_samp_inv_t() {
    __shared__ float2 T[16][273];
    int tid = threadIdx.x;
    int tx = tid & 15, q = tid >> 4;
    int ux = blockIdx.x * 16 + tx, uy = blockIdx.y, v = blockIdx.z;

    // zero staging (covers t=0 and t in [128,256))
    for (int i = tid; i < 16 * 273; i += 256)
        ((float2*)T)[i] = make_float2(0.f, 0.f);
    __syncthreads();

    int iy = (uy + 128) & 255;       // shifted coords (for the Stolt mapping)
    int ix = (ux + 128) & 255;
    float gx = (float)(ix - 128) * (1.0f / 128.0f);
    float gy = (float)(iy - 128) * (1.0f / 128.0f);
    float rxy = 0.1024f * (gx * gx + gy * gy);

    // filtered spectrum is in UNSHIFTED layout: read at (uy, ux)
    const float2* __restrict__ G =
        g_A + (size_t)v * LL * LL * LL + (size_t)uy * LL + ux;

    int zprev = -9;
    float2 S0 = make_float2(0.f, 0.f), S1 = make_float2(0.f, 0.f);
    int t0 = (q == 0) ? 1 : q * 8;
    int t1 = q * 8 + 8;
    for (int t = t0; t < t1; ++t) {
        float gz = (float)t * (1.0f / 128.0f);
        float gzn = sqrtf(rxy + gz * gz);
        float pzf = 128.0f * gzn + 127.5f;   // >= 128.5 always
        int z0 = (int)pzf;
        float dz = pzf - (float)z0;
        if (z0 == zprev) {
            // planes cached
        } else if (z0 == zprev + 1) {
            S0 = S1;
            S1 = (z0 <= 254) ? G[(size_t)(z0 - 127) * LL * LL] : make_float2(0.f, 0.f);
        } else {
            S0 = (z0 <= 255) ? G[(size_t)(z0 - 128) * LL * LL] : make_float2(0.f, 0.f);
            S1 = (z0 <= 254) ? G[(size_t)(z0 - 127) * LL * LL] : make_float2(0.f, 0.f);
        }
        zprev = z0;
        float sc = gz / (gzn + 1e-8f);
        T[tx][t + (t >> 4)] = make_float2((S0.x * (1.f - dz) + S1.x * dz) * sc,
                                          (S0.y * (1.f - dz) + S1.y * dz) * sc);
    }
    __syncthreads();

    int j = q;
    float2 r[16];
#pragma unroll
    for (int n1 = 0; n1 < 16; ++n1)
        r[BR4[n1]] = T[tx][17 * n1 + j];   // pidx(16*n1+j) = 17*n1+j
    fft256_pass(r, T[tx], j, -1.0f);

    size_t baseB = (size_t)v * LL * LL * LL + (size_t)uy * LL + ux;
#pragma unroll
    for (int k2 = 0; k2 < 8; ++k2)
        g_B[baseB + (size_t)(j + 16 * k2) * LL * LL] = r[k2];
}

// ---------------- Pass 5: inverse h-FFT (reads all h, writes h<128) ---------
__global__ void k_inv_h() {
    __shared__ float2 T[16][273];
    int tid = threadIdx.x;
    int tx = tid & 15, j = tid >> 4;
    int x = blockIdx.x * 16 + tx, t = blockIdx.y, v = blockIdx.z;
    size_t base = ((size_t)v * LL + t) * LL * LL + x;
    float2 r[16];
#pragma unroll
    for (int n1 = 0; n1 < 16; ++n1)
        r[BR4[n1]] = g_B[base + (size_t)(16 * n1 + j) * LL];
    fft256_pass(r, T[tx], j, -1.0f);
#pragma unroll
    for (int k2 = 0; k2 < 8; ++k2)
        g_B[base + (size_t)(j + 16 * k2) * LL] = r[k2];
}

// ---------------- Pass 6: inverse x-FFT + real crop + normalize -------------
__global__ void k_inv_x(float* __restrict__ out) {
    __shared__ float2 T[16][273];
    int tid = threadIdx.x;
    int j = tid & 15, ln = tid >> 4;
    int h = blockIdx.x * 16 + ln, t = blockIdx.y, v = blockIdx.z;
    size_t base = (((size_t)v * LL + t) * LL + h) * LL;
    float2 r[16];
#pragma unroll
    for (int n1 = 0; n1 < 16; ++n1)
        r[BR4[n1]] = g_B[base + 16 * n1 + j];
    fft256_pass(r, T[ln], j, -1.0f);
    float* dst = out + (((size_t)v * 128 + t) * 128 + h) * 128;
#pragma unroll
    for (int k2 = 0; k2 < 8; ++k2)
        dst[j + 16 * k2] = r[k2].x * (1.0f / 16777216.0f);
}

extern "C" void kernel_launch(void* const* d_in, const int* in_sizes, int n_in,
                              void* d_out, int out_size) {
    (void)in_sizes; (void)n_in; (void)out_size;
    const float* in = (const float*)d_in[0];
    float* out = (float*)d_out;

    k_fwd_x<<<dim3(8, 128, VOLS), 256>>>(in);
    k_fwd_h<<<dim3(16, 128, VOLS), 256>>>();
    k_fwd_t<<<dim3(16, 256, VOLS), 256>>>();
    k_samp_inv_t<<<dim3(16, 256, VOLS), 256>>>();
    k_inv_h<<<dim3(16, 128, VOLS), 256>>>();
    k_inv_x<<<dim3(8, 128, VOLS), 256>>>(out);
}

// round 5
// speedup vs baseline: 4.0697x; 1.2232x over previous
#include <cuda_runtime.h>
#include <cstdint>

// lct_fk round 5:
//  - forward t-FFT + Stolt z-resample + inverse t-FFT fused into ONE kernel
//    (the resample at column (uy,ux) only needs the spectrum column at the
//    same (h,x) -> fully local in smem; g_B eliminated; in-place on g_A).
//  - twiddles via 1-sincos complex recurrence instead of 15 sincos per pass.
//  - x/y half-sample stencil remains folded into fwd passes as the exact
//    circular pair filter G[k]=0.5(X[k]+X[k-1]) (exception G[128]=0.5*X[128]).

#define LL 256
#define VOLS 2

__device__ float2 g_A[(size_t)VOLS * LL * LL * LL];

__device__ const int BR4[16] = {0,8,4,12,2,10,6,14,1,9,5,13,3,11,7,15};

// ---------------- 16-pt in-register DIT FFT (input bit-reversed) ------------
__device__ __forceinline__ void fft16(float2 r[16], float dir) {
    const float CT[8] = {1.f, 0.92387953f, 0.70710678f, 0.38268343f,
                         0.f, -0.38268343f, -0.70710678f, -0.92387953f};
    const float ST[8] = {0.f, -0.38268343f, -0.70710678f, -0.92387953f,
                         -1.f, -0.92387953f, -0.70710678f, -0.38268343f};
#pragma unroll
    for (int s = 1; s <= 4; ++s) {
        int half = 1 << (s - 1);
#pragma unroll
        for (int j = 0; j < 8; ++j) {
            int k = j & (half - 1);
            int i0 = ((j >> (s - 1)) << s) + k;
            int i1 = i0 + half;
            float cs = CT[k << (4 - s)];
            float sn = dir * ST[k << (4 - s)];
            float2 b = r[i1];
            float tx = b.x * cs - b.y * sn;
            float ty = b.x * sn + b.y * cs;
            float2 a = r[i0];
            r[i1] = make_float2(a.x - tx, a.y - ty);
            r[i0] = make_float2(a.x + tx, a.y + ty);
        }
    }
}

// inter-pass twiddle via recurrence: r[k1] *= exp(dir * -2*pi*i * j*k1/256)
__device__ __forceinline__ void twiddle16(float2 r[16], int j, float dir) {
    float wy, wx;
    __sincosf(dir * -0.024543692606f * (float)j, &wy, &wx); // w = e^{dir*-2pi i j/256}
    float cx = wx, cy = wy;                                  // c = w^1
#pragma unroll
    for (int k1 = 1; k1 < 16; ++k1) {
        float2 a = r[k1];
        r[k1] = make_float2(a.x * cx - a.y * cy, a.x * cy + a.y * cx);
        float nx = cx * wx - cy * wy;
        float ny = cx * wy + cy * wx;
        cx = nx; cy = ny;
    }
}

// Full 256-pt FFT for one line handled by 16 threads (role j).
// Entry: r[BR4[n1]] = x[16*n1 + j]. Exit: r[k2] = X[j + 16*k2].
__device__ __forceinline__ void fft256_pass(float2 r[16], float2* Tline,
                                            int j, float dir) {
    fft16(r, dir);
    twiddle16(r, j, dir);
    __syncthreads();
#pragma unroll
    for (int k1 = 0; k1 < 16; ++k1) Tline[k1 * 17 + j] = r[k1];
    __syncthreads();
    float2 rr[16];
#pragma unroll
    for (int n2 = 0; n2 < 16; ++n2) rr[BR4[n2]] = Tline[j * 17 + n2];
    fft16(rr, dir);
#pragma unroll
    for (int k = 0; k < 16; ++k) r[k] = rr[k];
}

// ---------------- Pass 1: preprocess + x-FFT + x-filter ---------------------
__global__ void k_fwd_x(const float* __restrict__ in) {
    __shared__ float2 T[16][273];
    int tid = threadIdx.x;
    int j = tid & 15, ln = tid >> 4;
    int h = blockIdx.x * 16 + ln, t = blockIdx.y, v = blockIdx.z;
    float g = (float)t * (1.0f / 127.0f);
    const float* src = in + (((size_t)v * 128 + t) * 128 + h) * 128;
    float2 r[16];
#pragma unroll
    for (int n1 = 0; n1 < 16; ++n1) {
        float val = 0.0f;
        if (n1 < 8) {
            float f = src[16 * n1 + j];
            float xx = f * g * g;
            val = (xx > 0.0f) ? sqrtf(xx) : 0.0f;
        }
        r[BR4[n1]] = make_float2(val, 0.0f);
    }
    fft256_pass(r, T[ln], j, 1.0f);
    __syncthreads();
#pragma unroll
    for (int k2 = 0; k2 < 16; ++k2) T[ln][j + 17 * k2] = r[k2]; // pidx(k)=k+(k>>4)
    __syncthreads();
    float2* dst = g_A + (((size_t)v * LL + t) * LL + h) * LL;
#pragma unroll
    for (int k2 = 0; k2 < 16; ++k2) {
        int k = j + 16 * k2;
        float2 a = T[ln][k + (k >> 4)];
        float2 b = make_float2(0.f, 0.f);
        if (k != 128) { int km = (k - 1) & 255; b = T[ln][km + (km >> 4)]; }
        dst[k] = make_float2(0.5f * (a.x + b.x), 0.5f * (a.y + b.y));
    }
}

// ---------------- Pass 2: h-FFT (reads h<128) + y-filter, writes all h ------
__global__ void k_fwd_h() {
    __shared__ float2 T[16][273];
    int tid = threadIdx.x;
    int tx = tid & 15, j = tid >> 4;
    int x = blockIdx.x * 16 + tx, t = blockIdx.y, v = blockIdx.z;
    size_t base = ((size_t)v * LL + t) * LL * LL + x;
    float2 r[16];
#pragma unroll
    for (int n1 = 0; n1 < 16; ++n1) {
        int hh = 16 * n1 + j;
        r[BR4[n1]] = (n1 < 8) ? g_A[base + (size_t)hh * LL] : make_float2(0.f, 0.f);
    }
    fft256_pass(r, T[tx], j, 1.0f);
    __syncthreads();
#pragma unroll
    for (int k2 = 0; k2 < 16; ++k2) T[tx][j + 17 * k2] = r[k2];
    __syncthreads();
#pragma unroll
    for (int k2 = 0; k2 < 16; ++k2) {
        int k = j + 16 * k2;
        float2 a = T[tx][k + (k >> 4)];
        float2 b = make_float2(0.f, 0.f);
        if (k != 128) { int km = (k - 1) & 255; b = T[tx][km + (km >> 4)]; }
        g_A[base + (size_t)k * LL] =
            make_float2(0.5f * (a.x + b.x), 0.5f * (a.y + b.y));
    }
}

// ---- Pass 3 (fused): forward t-FFT -> Stolt z-resample -> inverse t-FFT ----
// In place on g_A; only t<128 planes touched.
__global__ void k_t_samp() {
    __shared__ float2 T[16][273];
    int tid = threadIdx.x;
    int tx = tid & 15, j = tid >> 4;
    int x = blockIdx.x * 16 + tx, h = blockIdx.y, v = blockIdx.z;
    size_t base = (size_t)v * LL * LL * LL + (size_t)h * LL + x;

    float2 r[16];
#pragma unroll
    for (int n1 = 0; n1 < 16; ++n1) {
        int tt = 16 * n1 + j;
        r[BR4[n1]] = (n1 < 8) ? g_A[base + (size_t)tt * LL * LL]
                              : make_float2(0.f, 0.f);
    }
    fft256_pass(r, T[tx], j, 1.0f);       // F[k] in r[k2], k = j+16*k2

    // stash the 128 needed spectrum values (k<128) into smem
    __syncthreads();
#pragma unroll
    for (int k2 = 0; k2 < 8; ++k2) {
        int k = j + 16 * k2;
        T[tx][k + (k >> 4)] = r[k2];
    }
    __syncthreads();

    // Stolt resample for this column: uy=h, ux=x (unshifted layout)
    int iy = (h + 128) & 255;
    int ixs = (x + 128) & 255;
    float gx = (float)(ixs - 128) * (1.0f / 128.0f);
    float gy = (float)(iy - 128) * (1.0f / 128.0f);
    float rxy = 0.1024f * (gx * gx + gy * gy);

#pragma unroll
    for (int n1 = 0; n1 < 16; ++n1) {
        int t = 16 * n1 + j;
        float2 s = make_float2(0.f, 0.f);
        if (t >= 1 && t < 128) {
            float gz = (float)t * (1.0f / 128.0f);
            float gzn = sqrtf(rxy + gz * gz);
            float pzf = 128.0f * gzn + 127.5f;   // >= 128.5
            int z0 = (int)pzf;
            float dz = pzf - (float)z0;
            int p0 = z0 - 128, p1 = z0 - 127;    // p0 >= 0
            float2 S0 = (p0 <= 127) ? T[tx][p0 + (p0 >> 4)] : make_float2(0.f, 0.f);
            float2 S1 = (p1 <= 127) ? T[tx][p1 + (p1 >> 4)] : make_float2(0.f, 0.f);
            float sc = gz / (gzn + 1e-8f);
            s = make_float2((S0.x * (1.f - dz) + S1.x * dz) * sc,
                            (S0.y * (1.f - dz) + S1.y * dz) * sc);
        }
        r[BR4[n1]] = s;
    }
    // first __syncthreads inside fft256_pass orders sampling reads vs T reuse
    fft256_pass(r, T[tx], j, -1.0f);

#pragma unroll
    for (int k2 = 0; k2 < 8; ++k2)
        g_A[base + (size_t)(j + 16 * k2) * LL * LL] = r[k2];
}

// ---------------- Pass 4: inverse h-FFT (reads all h, writes h<128) ---------
__global__ void k_inv_h() {
    __shared__ float2 T[16][273];
    int tid = threadIdx.x;
    int tx = tid & 15, j = tid >> 4;
    int x = blockIdx.x * 16 + tx, t = blockIdx.y, v = blockIdx.z;
    size_t base = ((size_t)v * LL + t) * LL * LL + x;
    float2 r[16];
#pragma unroll
    for (int n1 = 0; n1 < 16; ++n1)
        r[BR4[n1]] = g_A[base + (size_t)(16 * n1 + j) * LL];
    fft256_pass(r, T[tx], j, -1.0f);
#pragma unroll
    for (int k2 = 0; k2 < 8; ++k2)
        g_A[base + (size_t)(j + 16 * k2) * LL] = r[k2];
}

// ---------------- Pass 5: inverse x-FFT + real crop + normalize -------------
__global__ void k_inv_x(float* __restrict__ out) {
    __shared__ float2 T[16][273];
    int tid = threadIdx.x;
    int j = tid & 15, ln = tid >> 4;
    int h = blockIdx.x * 16 + ln, t = blockIdx.y, v = blockIdx.z;
    size_t base = (((size_t)v * LL + t) * LL + h) * LL;
    float2 r[16];
#pragma unroll
    for (int n1 = 0; n1 < 16; ++n1)
        r[BR4[n1]] = g_A[base + 16 * n1 + j];
    fft256_pass(r, T[ln], j, -1.0f);
    float* dst = out + (((size_t)v * 128 + t) * 128 + h) * 128;
#pragma unroll
    for (int k2 = 0; k2 < 8; ++k2)
        dst[j + 16 * k2] = r[k2].x * (1.0f / 16777216.0f);
}

extern "C" void kernel_launch(void* const* d_in, const int* in_sizes, int n_in,
                              void* d_out, int out_size) {
    (void)in_sizes; (void)n_in; (void)out_size;
    const float* in = (const float*)d_in[0];
    float* out = (float*)d_out;

    k_fwd_x<<<dim3(8, 128, VOLS), 256>>>(in);
    k_fwd_h<<<dim3(16, 128, VOLS), 256>>>();
    k_t_samp<<<dim3(16, 256, VOLS), 256>>>();
    k_inv_h<<<dim3(16, 128, VOLS), 256>>>();
    k_inv_x<<<dim3(8, 128, VOLS), 256>>>(out);
}

// round 6
// speedup vs baseline: 4.5894x; 1.1277x over previous
#include <cuda_runtime.h>
#include <cuda_fp16.h>
#include <cstdint>

// lct_fk round 6: fp16 (half2) inter-pass storage, fp32 compute.
// Normalization 1/2^24 folded progressively: 1/4096 at t_samp store,
// 1/4096 at inv_h store (keeps every stored stage within fp16 range).
// Structure identical to round 5 (which passed at 213us / 1.6e-6).

#define LL 256
#define VOLS 2

__device__ __half2 g_A[(size_t)VOLS * LL * LL * LL]; // 134 MB

__device__ const int BR4[16] = {0,8,4,12,2,10,6,14,1,9,5,13,3,11,7,15};

__device__ __forceinline__ float2 h2f(__half2 h) { return __half22float2(h); }
__device__ __forceinline__ __half2 f2h(float2 f) { return __floats2half2_rn(f.x, f.y); }

// ---------------- 16-pt in-register DIT FFT (input bit-reversed) ------------
__device__ __forceinline__ void fft16(float2 r[16], float dir) {
    const float CT[8] = {1.f, 0.92387953f, 0.70710678f, 0.38268343f,
                         0.f, -0.38268343f, -0.70710678f, -0.92387953f};
    const float ST[8] = {0.f, -0.38268343f, -0.70710678f, -0.92387953f,
                         -1.f, -0.92387953f, -0.70710678f, -0.38268343f};
#pragma unroll
    for (int s = 1; s <= 4; ++s) {
        int half = 1 << (s - 1);
#pragma unroll
        for (int j = 0; j < 8; ++j) {
            int k = j & (half - 1);
            int i0 = ((j >> (s - 1)) << s) + k;
            int i1 = i0 + half;
            float cs = CT[k << (4 - s)];
            float sn = dir * ST[k << (4 - s)];
            float2 b = r[i1];
            float tx = b.x * cs - b.y * sn;
            float ty = b.x * sn + b.y * cs;
            float2 a = r[i0];
            r[i1] = make_float2(a.x - tx, a.y - ty);
            r[i0] = make_float2(a.x + tx, a.y + ty);
        }
    }
}

// inter-pass twiddle via recurrence: r[k1] *= exp(dir * -2*pi*i * j*k1/256)
__device__ __forceinline__ void twiddle16(float2 r[16], int j, float dir) {
    float wy, wx;
    __sincosf(dir * -0.024543692606f * (float)j, &wy, &wx);
    float cx = wx, cy = wy;
#pragma unroll
    for (int k1 = 1; k1 < 16; ++k1) {
        float2 a = r[k1];
        r[k1] = make_float2(a.x * cx - a.y * cy, a.x * cy + a.y * cx);
        float nx = cx * wx - cy * wy;
        float ny = cx * wy + cy * wx;
        cx = nx; cy = ny;
    }
}

// Full 256-pt FFT for one line handled by 16 threads (role j).
// Entry: r[BR4[n1]] = x[16*n1 + j]. Exit: r[k2] = X[j + 16*k2].
__device__ __forceinline__ void fft256_pass(float2 r[16], float2* Tline,
                                            int j, float dir) {
    fft16(r, dir);
    twiddle16(r, j, dir);
    __syncthreads();
#pragma unroll
    for (int k1 = 0; k1 < 16; ++k1) Tline[k1 * 17 + j] = r[k1];
    __syncthreads();
    float2 rr[16];
#pragma unroll
    for (int n2 = 0; n2 < 16; ++n2) rr[BR4[n2]] = Tline[j * 17 + n2];
    fft16(rr, dir);
#pragma unroll
    for (int k = 0; k < 16; ++k) r[k] = rr[k];
}

// ---------------- Pass 1: preprocess + x-FFT + x-filter ---------------------
__global__ void k_fwd_x(const float* __restrict__ in) {
    __shared__ float2 T[16][273];
    int tid = threadIdx.x;
    int j = tid & 15, ln = tid >> 4;
    int h = blockIdx.x * 16 + ln, t = blockIdx.y, v = blockIdx.z;
    float g = (float)t * (1.0f / 127.0f);
    const float* src = in + (((size_t)v * 128 + t) * 128 + h) * 128;
    float2 r[16];
#pragma unroll
    for (int n1 = 0; n1 < 16; ++n1) {
        float val = 0.0f;
        if (n1 < 8) {
            float f = src[16 * n1 + j];
            float xx = f * g * g;
            val = (xx > 0.0f) ? sqrtf(xx) : 0.0f;
        }
        r[BR4[n1]] = make_float2(val, 0.0f);
    }
    fft256_pass(r, T[ln], j, 1.0f);
    __syncthreads();
#pragma unroll
    for (int k2 = 0; k2 < 16; ++k2) T[ln][j + 17 * k2] = r[k2]; // pidx(k)=k+(k>>4)
    __syncthreads();
    __half2* dst = g_A + (((size_t)v * LL + t) * LL + h) * LL;
#pragma unroll
    for (int k2 = 0; k2 < 16; ++k2) {
        int k = j + 16 * k2;
        float2 a = T[ln][k + (k >> 4)];
        float2 b = make_float2(0.f, 0.f);
        if (k != 128) { int km = (k - 1) & 255; b = T[ln][km + (km >> 4)]; }
        dst[k] = f2h(make_float2(0.5f * (a.x + b.x), 0.5f * (a.y + b.y)));
    }
}

// ---------------- Pass 2: h-FFT (reads h<128) + y-filter, writes all h ------
__global__ void k_fwd_h() {
    __shared__ float2 T[16][273];
    int tid = threadIdx.x;
    int tx = tid & 15, j = tid >> 4;
    int x = blockIdx.x * 16 + tx, t = blockIdx.y, v = blockIdx.z;
    size_t base = ((size_t)v * LL + t) * LL * LL + x;
    float2 r[16];
#pragma unroll
    for (int n1 = 0; n1 < 16; ++n1) {
        int hh = 16 * n1 + j;
        r[BR4[n1]] = (n1 < 8) ? h2f(g_A[base + (size_t)hh * LL])
                              : make_float2(0.f, 0.f);
    }
    fft256_pass(r, T[tx], j, 1.0f);
    __syncthreads();
#pragma unroll
    for (int k2 = 0; k2 < 16; ++k2) T[tx][j + 17 * k2] = r[k2];
    __syncthreads();
#pragma unroll
    for (int k2 = 0; k2 < 16; ++k2) {
        int k = j + 16 * k2;
        float2 a = T[tx][k + (k >> 4)];
        float2 b = make_float2(0.f, 0.f);
        if (k != 128) { int km = (k - 1) & 255; b = T[tx][km + (km >> 4)]; }
        g_A[base + (size_t)k * LL] =
            f2h(make_float2(0.5f * (a.x + b.x), 0.5f * (a.y + b.y)));
    }
}

// ---- Pass 3 (fused): forward t-FFT -> Stolt z-resample -> inverse t-FFT ----
__global__ void k_t_samp() {
    __shared__ float2 T[16][273];
    int tid = threadIdx.x;
    int tx = tid & 15, j = tid >> 4;
    int x = blockIdx.x * 16 + tx, h = blockIdx.y, v = blockIdx.z;
    size_t base = (size_t)v * LL * LL * LL + (size_t)h * LL + x;

    float2 r[16];
#pragma unroll
    for (int n1 = 0; n1 < 16; ++n1) {
        int tt = 16 * n1 + j;
        r[BR4[n1]] = (n1 < 8) ? h2f(g_A[base + (size_t)tt * LL * LL])
                              : make_float2(0.f, 0.f);
    }
    fft256_pass(r, T[tx], j, 1.0f);       // F[k] in r[k2], k = j+16*k2

    __syncthreads();
#pragma unroll
    for (int k2 = 0; k2 < 8; ++k2) {
        int k = j + 16 * k2;
        T[tx][k + (k >> 4)] = r[k2];      // stash k<128 spectrum
    }
    __syncthreads();

    int iy = (h + 128) & 255;
    int ixs = (x + 128) & 255;
    float gx = (float)(ixs - 128) * (1.0f / 128.0f);
    float gy = (float)(iy - 128) * (1.0f / 128.0f);
    float rxy = 0.1024f * (gx * gx + gy * gy);

#pragma unroll
    for (int n1 = 0; n1 < 16; ++n1) {
        int t = 16 * n1 + j;
        float2 s = make_float2(0.f, 0.f);
        if (t >= 1 && t < 128) {
            float gz = (float)t * (1.0f / 128.0f);
            float gzn = sqrtf(rxy + gz * gz);
            float pzf = 128.0f * gzn + 127.5f;   // >= 128.5
            int z0 = (int)pzf;
            float dz = pzf - (float)z0;
            int p0 = z0 - 128, p1 = z0 - 127;    // p0 >= 0
            float2 S0 = (p0 <= 127) ? T[tx][p0 + (p0 >> 4)] : make_float2(0.f, 0.f);
            float2 S1 = (p1 <= 127) ? T[tx][p1 + (p1 >> 4)] : make_float2(0.f, 0.f);
            float sc = gz / (gzn + 1e-8f);
            s = make_float2((S0.x * (1.f - dz) + S1.x * dz) * sc,
                            (S0.y * (1.f - dz) + S1.y * dz) * sc);
        }
        r[BR4[n1]] = s;
    }
    fft256_pass(r, T[tx], j, -1.0f);

    const float SC = 1.0f / 4096.0f;      // first chunk of 1/2^24
#pragma unroll
    for (int k2 = 0; k2 < 8; ++k2)
        g_A[base + (size_t)(j + 16 * k2) * LL * LL] =
            f2h(make_float2(r[k2].x * SC, r[k2].y * SC));
}

// ---------------- Pass 4: inverse h-FFT (reads all h, writes h<128) ---------
__global__ void k_inv_h() {
    __shared__ float2 T[16][273];
    int tid = threadIdx.x;
    int tx = tid & 15, j = tid >> 4;
    int x = blockIdx.x * 16 + tx, t = blockIdx.y, v = blockIdx.z;
    size_t base = ((size_t)v * LL + t) * LL * LL + x;
    float2 r[16];
#pragma unroll
    for (int n1 = 0; n1 < 16; ++n1)
        r[BR4[n1]] = h2f(g_A[base + (size_t)(16 * n1 + j) * LL]);
    fft256_pass(r, T[tx], j, -1.0f);
    const float SC = 1.0f / 4096.0f;      // second chunk of 1/2^24
#pragma unroll
    for (int k2 = 0; k2 < 8; ++k2)
        g_A[base + (size_t)(j + 16 * k2) * LL] =
            f2h(make_float2(r[k2].x * SC, r[k2].y * SC));
}

// ---------------- Pass 5: inverse x-FFT + real crop ------------------------
__global__ void k_inv_x(float* __restrict__ out) {
    __shared__ float2 T[16][273];
    int tid = threadIdx.x;
    int j = tid & 15, ln = tid >> 4;
    int h = blockIdx.x * 16 + ln, t = blockIdx.y, v = blockIdx.z;
    size_t base = (((size_t)v * LL + t) * LL + h) * LL;
    float2 r[16];
#pragma unroll
    for (int n1 = 0; n1 < 16; ++n1)
        r[BR4[n1]] = h2f(g_A[base + 16 * n1 + j]);
    fft256_pass(r, T[ln], j, -1.0f);
    float* dst = out + (((size_t)v * 128 + t) * 128 + h) * 128;
#pragma unroll
    for (int k2 = 0; k2 < 8; ++k2)
        dst[j + 16 * k2] = r[k2].x;       // normalization fully folded upstream
}

extern "C" void kernel_launch(void* const* d_in, const int* in_sizes, int n_in,
                              void* d_out, int out_size) {
    (void)in_sizes; (void)n_in; (void)out_size;
    const float* in = (const float*)d_in[0];
    float* out = (float*)d_out;

    k_fwd_x<<<dim3(8, 128, VOLS), 256>>>(in);
    k_fwd_h<<<dim3(16, 128, VOLS), 256>>>();
    k_t_samp<<<dim3(16, 256, VOLS), 256>>>();
    k_inv_h<<<dim3(16, 128, VOLS), 256>>>();
    k_inv_x<<<dim3(8, 128, VOLS), 256>>>(out);
}

// round 7
// speedup vs baseline: 4.6928x; 1.0225x over previous
#include <cuda_runtime.h>
#include <cuda_fp16.h>
#include <cstdint>

// lct_fk round 7: round-6 structure (fp16 interstage, fused t-pipeline) plus
// instruction diet: 32-bit unsigned addressing everywhere (offsets < 2^27),
// rsqrt-based Stolt math (1 MUFU instead of sqrt+div).

#define LL 256u
#define VOLS 2

__device__ __half2 g_A[(size_t)VOLS * LL * LL * LL]; // 134 MB

__device__ const int BR4[16] = {0,8,4,12,2,10,6,14,1,9,5,13,3,11,7,15};

__device__ __forceinline__ float2 h2f(__half2 h) { return __half22float2(h); }
__device__ __forceinline__ __half2 f2h(float2 f) { return __floats2half2_rn(f.x, f.y); }

// ---------------- 16-pt in-register DIT FFT (input bit-reversed) ------------
__device__ __forceinline__ void fft16(float2 r[16], float dir) {
    const float CT[8] = {1.f, 0.92387953f, 0.70710678f, 0.38268343f,
                         0.f, -0.38268343f, -0.70710678f, -0.92387953f};
    const float ST[8] = {0.f, -0.38268343f, -0.70710678f, -0.92387953f,
                         -1.f, -0.92387953f, -0.70710678f, -0.38268343f};
#pragma unroll
    for (int s = 1; s <= 4; ++s) {
        int half = 1 << (s - 1);
#pragma unroll
        for (int j = 0; j < 8; ++j) {
            int k = j & (half - 1);
            int i0 = ((j >> (s - 1)) << s) + k;
            int i1 = i0 + half;
            float cs = CT[k << (4 - s)];
            float sn = dir * ST[k << (4 - s)];
            float2 b = r[i1];
            float tx = b.x * cs - b.y * sn;
            float ty = b.x * sn + b.y * cs;
            float2 a = r[i0];
            r[i1] = make_float2(a.x - tx, a.y - ty);
            r[i0] = make_float2(a.x + tx, a.y + ty);
        }
    }
}

// inter-pass twiddle via recurrence: r[k1] *= exp(dir * -2*pi*i * j*k1/256)
__device__ __forceinline__ void twiddle16(float2 r[16], int j, float dir) {
    float wy, wx;
    __sincosf(dir * -0.024543692606f * (float)j, &wy, &wx);
    float cx = wx, cy = wy;
#pragma unroll
    for (int k1 = 1; k1 < 16; ++k1) {
        float2 a = r[k1];
        r[k1] = make_float2(a.x * cx - a.y * cy, a.x * cy + a.y * cx);
        float nx = cx * wx - cy * wy;
        float ny = cx * wy + cy * wx;
        cx = nx; cy = ny;
    }
}

// Full 256-pt FFT for one line handled by 16 threads (role j).
// Entry: r[BR4[n1]] = x[16*n1 + j]. Exit: r[k2] = X[j + 16*k2].
__device__ __forceinline__ void fft256_pass(float2 r[16], float2* Tline,
                                            int j, float dir) {
    fft16(r, dir);
    twiddle16(r, j, dir);
    __syncthreads();
#pragma unroll
    for (int k1 = 0; k1 < 16; ++k1) Tline[k1 * 17 + j] = r[k1];
    __syncthreads();
    float2 rr[16];
#pragma unroll
    for (int n2 = 0; n2 < 16; ++n2) rr[BR4[n2]] = Tline[j * 17 + n2];
    fft16(rr, dir);
#pragma unroll
    for (int k = 0; k < 16; ++k) r[k] = rr[k];
}

// ---------------- Pass 1: preprocess + x-FFT + x-filter ---------------------
__global__ void k_fwd_x(const float* __restrict__ in) {
    __shared__ float2 T[16][273];
    int tid = threadIdx.x;
    int j = tid & 15, ln = tid >> 4;
    unsigned h = blockIdx.x * 16 + ln, t = blockIdx.y, v = blockIdx.z;
    float g = (float)t * (1.0f / 127.0f);
    const float* src = in + (((v * 128u + t) * 128u + h) * 128u);
    float2 r[16];
#pragma unroll
    for (int n1 = 0; n1 < 16; ++n1) {
        float val = 0.0f;
        if (n1 < 8) {
            float f = src[16 * n1 + j];
            float xx = f * g * g;
            val = (xx > 0.0f) ? sqrtf(xx) : 0.0f;
        }
        r[BR4[n1]] = make_float2(val, 0.0f);
    }
    fft256_pass(r, T[ln], j, 1.0f);
    __syncthreads();
#pragma unroll
    for (int k2 = 0; k2 < 16; ++k2) T[ln][j + 17 * k2] = r[k2]; // pidx(k)=k+(k>>4)
    __syncthreads();
    __half2* __restrict__ dst = g_A + (((v * LL + t) * LL + h) * LL);
#pragma unroll
    for (int k2 = 0; k2 < 16; ++k2) {
        int k = j + 16 * k2;
        float2 a = T[ln][k + (k >> 4)];
        float2 b = make_float2(0.f, 0.f);
        if (k != 128) { int km = (k - 1) & 255; b = T[ln][km + (km >> 4)]; }
        dst[k] = f2h(make_float2(0.5f * (a.x + b.x), 0.5f * (a.y + b.y)));
    }
}

// ---------------- Pass 2: h-FFT (reads h<128) + y-filter, writes all h ------
__global__ void k_fwd_h() {
    __shared__ float2 T[16][273];
    int tid = threadIdx.x;
    int tx = tid & 15, j = tid >> 4;
    unsigned x = blockIdx.x * 16 + tx, t = blockIdx.y, v = blockIdx.z;
    unsigned base = (v * LL + t) * LL * LL + x;
    float2 r[16];
#pragma unroll
    for (int n1 = 0; n1 < 16; ++n1) {
        unsigned hh = 16 * n1 + j;
        r[BR4[n1]] = (n1 < 8) ? h2f(g_A[base + hh * LL])
                              : make_float2(0.f, 0.f);
    }
    fft256_pass(r, T[tx], j, 1.0f);
    __syncthreads();
#pragma unroll
    for (int k2 = 0; k2 < 16; ++k2) T[tx][j + 17 * k2] = r[k2];
    __syncthreads();
#pragma unroll
    for (int k2 = 0; k2 < 16; ++k2) {
        int k = j + 16 * k2;
        float2 a = T[tx][k + (k >> 4)];
        float2 b = make_float2(0.f, 0.f);
        if (k != 128) { int km = (k - 1) & 255; b = T[tx][km + (km >> 4)]; }
        g_A[base + (unsigned)k * LL] =
            f2h(make_float2(0.5f * (a.x + b.x), 0.5f * (a.y + b.y)));
    }
}

// ---- Pass 3 (fused): forward t-FFT -> Stolt z-resample -> inverse t-FFT ----
__global__ void k_t_samp() {
    __shared__ float2 T[16][273];
    int tid = threadIdx.x;
    int tx = tid & 15, j = tid >> 4;
    unsigned x = blockIdx.x * 16 + tx, h = blockIdx.y, v = blockIdx.z;
    unsigned base = v * LL * LL * LL + h * LL + x;

    float2 r[16];
#pragma unroll
    for (int n1 = 0; n1 < 16; ++n1) {
        unsigned tt = 16 * n1 + j;
        r[BR4[n1]] = (n1 < 8) ? h2f(g_A[base + tt * (LL * LL)])
                              : make_float2(0.f, 0.f);
    }
    fft256_pass(r, T[tx], j, 1.0f);       // F[k] in r[k2], k = j+16*k2

    __syncthreads();
#pragma unroll
    for (int k2 = 0; k2 < 8; ++k2) {
        int k = j + 16 * k2;
        T[tx][k + (k >> 4)] = r[k2];      // stash k<128 spectrum
    }
    __syncthreads();

    int iy = ((int)h + 128) & 255;
    int ixs = ((int)x + 128) & 255;
    float gx = (float)(ixs - 128) * (1.0f / 128.0f);
    float gy = (float)(iy - 128) * (1.0f / 128.0f);
    float rxy = 0.1024f * (gx * gx + gy * gy);

#pragma unroll
    for (int n1 = 0; n1 < 16; ++n1) {
        int t = 16 * n1 + j;
        float2 s = make_float2(0.f, 0.f);
        if (t >= 1 && t < 128) {
            float gz = (float)t * (1.0f / 128.0f);
            float q = rxy + gz * gz;       // >= (1/128)^2
            float rq = rsqrtf(q);
            float gzn = q * rq;            // sqrt(q)
            float pzf = 128.0f * gzn + 127.5f;   // >= 128.5
            int z0 = (int)pzf;
            float dz = pzf - (float)z0;
            int p0 = z0 - 128, p1 = z0 - 127;    // p0 >= 0
            float2 S0 = (p0 <= 127) ? T[tx][p0 + (p0 >> 4)] : make_float2(0.f, 0.f);
            float2 S1 = (p1 <= 127) ? T[tx][p1 + (p1 >> 4)] : make_float2(0.f, 0.f);
            float sc = gz * rq;            // ~ gz / gzn (1e-8 guard negligible)
            s = make_float2((S0.x * (1.f - dz) + S1.x * dz) * sc,
                            (S0.y * (1.f - dz) + S1.y * dz) * sc);
        }
        r[BR4[n1]] = s;
    }
    fft256_pass(r, T[tx], j, -1.0f);

    const float SC = 1.0f / 4096.0f;      // first chunk of 1/2^24
#pragma unroll
    for (int k2 = 0; k2 < 8; ++k2)
        g_A[base + (unsigned)(j + 16 * k2) * (LL * LL)] =
            f2h(make_float2(r[k2].x * SC, r[k2].y * SC));
}

// ---------------- Pass 4: inverse h-FFT (reads all h, writes h<128) ---------
__global__ void k_inv_h() {
    __shared__ float2 T[16][273];
    int tid = threadIdx.x;
    int tx = tid & 15, j = tid >> 4;
    unsigned x = blockIdx.x * 16 + tx, t = blockIdx.y, v = blockIdx.z;
    unsigned base = (v * LL + t) * LL * LL + x;
    float2 r[16];
#pragma unroll
    for (int n1 = 0; n1 < 16; ++n1)
        r[BR4[n1]] = h2f(g_A[base + (unsigned)(16 * n1 + j) * LL]);
    fft256_pass(r, T[tx], j, -1.0f);
    const float SC = 1.0f / 4096.0f;      // second chunk of 1/2^24
#pragma unroll
    for (int k2 = 0; k2 < 8; ++k2)
        g_A[base + (unsigned)(j + 16 * k2) * LL] =
            f2h(make_float2(r[k2].x * SC, r[k2].y * SC));
}

// ---------------- Pass 5: inverse x-FFT + real crop ------------------------
__global__ void k_inv_x(float* __restrict__ out) {
    __shared__ float2 T[16][273];
    int tid = threadIdx.x;
    int j = tid & 15, ln = tid >> 4;
    unsigned h = blockIdx.x * 16 + ln, t = blockIdx.y, v = blockIdx.z;
    unsigned base = ((v * LL + t) * LL + h) * LL;
    float2 r[16];
#pragma unroll
    for (int n1 = 0; n1 < 16; ++n1)
        r[BR4[n1]] = h2f(g_A[base + 16 * n1 + j]);
    fft256_pass(r, T[ln], j, -1.0f);
    float* dst = out + (((v * 128u + t) * 128u + h) * 128u);
#pragma unroll
    for (int k2 = 0; k2 < 8; ++k2)
        dst[j + 16 * k2] = r[k2].x;       // normalization fully folded upstream
}

extern "C" void kernel_launch(void* const* d_in, const int* in_sizes, int n_in,
                              void* d_out, int out_size) {
    (void)in_sizes; (void)n_in; (void)out_size;
    const float* in = (const float*)d_in[0];
    float* out = (float*)d_out;

    k_fwd_x<<<dim3(8, 128, VOLS), 256>>>(in);
    k_fwd_h<<<dim3(16, 128, VOLS), 256>>>();
    k_t_samp<<<dim3(16, 256, VOLS), 256>>>();
    k_inv_h<<<dim3(16, 128, VOLS), 256>>>();
    k_inv_x<<<dim3(8, 128, VOLS), 256>>>(out);
}